// round 2
// baseline (speedup 1.0000x reference)
#include <cuda_runtime.h>

#define N_   128
#define C_   64
#define CO_  64
#define T_   256
#define V_   25
#define R_   8
#define TT_  16
#define ADJP 28    // padded adj row (floats), even -> 8B-aligned u64 loads
#define X3S  424   // sx3 o-stride (floats): even, %32==8 -> conflict-free

// scratch (device globals -- no allocation allowed)
__device__ float g_xm[N_ * C_ * V_];            // [n][c][v]  t-sums
__device__ float g_adj[N_ * CO_ * V_ * ADJP];   // [n][o][u][28]

typedef unsigned long long u64;

__device__ __forceinline__ u64 pack2(float lo, float hi) {
    u64 r; asm("mov.b64 %0, {%1,%2};" : "=l"(r) : "f"(lo), "f"(hi)); return r;
}
__device__ __forceinline__ void unpack2(u64 v, float& lo, float& hi) {
    asm("mov.b64 {%0,%1}, %2;" : "=f"(lo), "=f"(hi) : "l"(v));
}
__device__ __forceinline__ u64 fma2(u64 a, u64 b, u64 c) {
    u64 d; asm("fma.rn.f32x2 %0, %1, %2, %3;" : "=l"(d) : "l"(a), "l"(b), "l"(c)); return d;
}

// ---------------------------------------------------------------------------
// Kernel 1: xm[n,c,v] = sum_t x[n,c,t,v]   (one coalesced pass over x)
// ---------------------------------------------------------------------------
__global__ void k1_tsum(const float* __restrict__ x) {
    __shared__ float tile[T_ * V_];
    __shared__ float part[8][V_];
    const int bx  = blockIdx.x;               // n*64 + c
    const int tid = threadIdx.x;

    const float4* src = reinterpret_cast<const float4*>(x + (size_t)bx * (T_ * V_));
    float4* dst = reinterpret_cast<float4*>(tile);
    for (int i = tid; i < (T_ * V_) / 4; i += 256) dst[i] = src[i];
    __syncthreads();

    if (tid < 200) {
        const int g = tid / 25, v = tid - g * 25;
        float s = 0.f;
        const int tb = g * 32;
        #pragma unroll 8
        for (int t = tb; t < tb + 32; ++t) s += tile[t * V_ + v];
        part[g][v] = s;
    }
    __syncthreads();

    if (tid < V_) {
        float s = 0.f;
        #pragma unroll
        for (int g = 0; g < 8; ++g) s += part[g][tid];
        g_xm[bx * V_ + tid] = s;
    }
}

// ---------------------------------------------------------------------------
// Kernel 2: adj[n,o,u,v] = sum_r W4[o,r]*tanh(x1[n,r,u]-x2[n,r,v]) + b4[o] + A[u,v]
// ---------------------------------------------------------------------------
__global__ void k2_adj(const float* __restrict__ A,
                       const float* __restrict__ W1, const float* __restrict__ b1,
                       const float* __restrict__ W2, const float* __restrict__ b2,
                       const float* __restrict__ W4, const float* __restrict__ b4) {
    __shared__ float sxm[C_ * V_];
    __shared__ float sx1[R_ * V_];
    __shared__ float sx2[R_ * V_];
    __shared__ float sW4[CO_ * R_];
    __shared__ float sA[V_ * V_];
    __shared__ float sb4[CO_];

    const int n = blockIdx.x, tid = threadIdx.x;
    for (int i = tid; i < C_ * V_;  i += 256) sxm[i] = g_xm[n * C_ * V_ + i];
    for (int i = tid; i < CO_ * R_; i += 256) sW4[i] = W4[i];
    for (int i = tid; i < V_ * V_;  i += 256) sA[i]  = A[i];
    if (tid < CO_) sb4[tid] = b4[tid];
    __syncthreads();

    if (tid < R_ * V_) {
        const int r = tid / V_, v = tid - r * V_;
        float s1 = 0.f, s2 = 0.f;
        for (int c = 0; c < C_; ++c) {
            const float xv = sxm[c * V_ + v];
            s1 = fmaf(W1[r * C_ + c], xv, s1);
            s2 = fmaf(W2[r * C_ + c], xv, s2);
        }
        sx1[tid] = s1 * (1.0f / T_) + b1[r];
        sx2[tid] = s2 * (1.0f / T_) + b2[r];
    }
    __syncthreads();

    for (int p = tid; p < V_ * V_; p += 256) {
        const int u = p / V_, v = p - u * V_;
        float y[R_];
        #pragma unroll
        for (int r = 0; r < R_; ++r) y[r] = tanhf(sx1[r * V_ + u] - sx2[r * V_ + v]);
        const float av = sA[p];
        float* out = &g_adj[((size_t)(n * CO_) * V_ + u) * ADJP + v];
        for (int o = 0; o < CO_; ++o) {
            float s = sb4[o];
            #pragma unroll
            for (int r = 0; r < R_; ++r) s = fmaf(sW4[o * R_ + r], y[r], s);
            out[(size_t)o * V_ * ADJP] = s + av;
        }
    }
}

// ---------------------------------------------------------------------------
// Kernel 3 (main), 512 threads: per block = (n, 16-timestep tile)
//   stage1: x3[o,t,v] = b3[o] + sum_c W3[o,c] x[n,c,t,v]   (f32x2)
//   stage2: z[n,o,t,u] = sum_v adj[n,o,u,v] x3[o,t,v]      (f32x2 over v-pairs)
// smem: sx [64][16][26] + sx3 [64][424] + sW3t [64][64] = 231,424 B
// ---------------------------------------------------------------------------
__global__ void __launch_bounds__(512, 1)
k3_main(const float* __restrict__ x, const float* __restrict__ W3,
        const float* __restrict__ b3, float* __restrict__ z) {
    extern __shared__ float sm[];
    float* sx   = sm;                       // 64*416 = 26624 floats, [c][t][26]
    float* sx3  = sm + 26624;               // 64*424 = 27136 floats, [o][t][26]
    float* sW3t = sm + 26624 + 27136;       // 64*64  = 4096 floats,  [c][o]

    const int bx  = blockIdx.x;
    const int n   = bx >> 4;
    const int t0  = (bx & 15) * TT_;
    const int tid = threadIdx.x;

    // W3 transposed into smem: sW3t[c][o]
    for (int i = tid; i < C_ * CO_; i += 512) {
        const int c = i >> 6, o = i & 63;
        sW3t[i] = W3[o * C_ + c];
    }
    // x tile: [c][t][26pad]
    const float* xg = x + ((size_t)n * C_ * T_ + t0) * V_;
    for (int q = tid; q < 64 * 100; q += 512) {
        const int c = q / 100, j = q - c * 100;
        const float4 val = *reinterpret_cast<const float4*>(xg + (size_t)c * (T_ * V_) + j * 4);
        const int e = j * 4;
        float fv[4] = {val.x, val.y, val.z, val.w};
        #pragma unroll
        for (int k = 0; k < 4; ++k) {
            const int ee = e + k;
            const int t = ee / 25, v = ee - t * 25;
            sx[c * (TT_ * 26) + t * 26 + v] = fv[k];
        }
    }
    __syncthreads();

    // ---- stage 1: thread = (o-pair, t); lane%16 = t -> perfect x wavefronts ----
    {
        const int t  = tid & 15;
        const int o0 = (tid >> 4) * 2;      // 0..62
        u64 acc[2][13];
        {
            const float ba = b3[o0], bb = b3[o0 + 1];
            #pragma unroll
            for (int j = 0; j < 13; ++j) { acc[0][j] = pack2(ba, ba); acc[1][j] = pack2(bb, bb); }
        }
        #pragma unroll 4
        for (int c = 0; c < C_; ++c) {
            const float2 w = *reinterpret_cast<const float2*>(&sW3t[c * 64 + o0]);
            const u64 w0 = pack2(w.x, w.x), w1 = pack2(w.y, w.y);
            const u64* xr = reinterpret_cast<const u64*>(&sx[c * (TT_ * 26) + t * 26]);
            u64 xv[13];
            #pragma unroll
            for (int j = 0; j < 13; ++j) xv[j] = xr[j];
            #pragma unroll
            for (int j = 0; j < 13; ++j) {
                acc[0][j] = fma2(xv[j], w0, acc[0][j]);
                acc[1][j] = fma2(xv[j], w1, acc[1][j]);
            }
        }
        #pragma unroll
        for (int i = 0; i < 2; ++i) {
            u64* dst = reinterpret_cast<u64*>(&sx3[(o0 + i) * X3S + t * 26]);
            #pragma unroll
            for (int j = 0; j < 13; ++j) dst[j] = acc[i][j];   // v=25 lane is pad
        }
    }
    __syncthreads();

    // ---- stage 2: thread = (o, ug); u = ug + 8k; f32x2 over v-pairs ----
    {
        const int o  = tid >> 3;
        const int ug = tid & 7;
        const int nrows = (ug == 0) ? 4 : 3;          // u=24 handled as row 3 of ug==0
        const float* x3row = &sx3[o * X3S];
        const float* abase = g_adj + (size_t)(n * CO_ + o) * (V_ * ADJP);
        float* zbase = z + ((size_t)(n * CO_ + o) * T_ + t0) * V_;

        #pragma unroll
        for (int pass = 0; pass < 2; ++pass) {
            const int r0 = pass * 2;
            const int np = (r0 + 2 <= nrows) ? 2 : (nrows - r0);   // 2, or 1 on pass1 ug!=0
            u64  ar[2][12];
            float ar24[2];
            #pragma unroll
            for (int rr = 0; rr < 2; ++rr) {
                if (rr < np) {
                    const int u = (r0 + rr) * 8 + ug;
                    const u64* ap = reinterpret_cast<const u64*>(abase + u * ADJP);
                    #pragma unroll
                    for (int j = 0; j < 12; ++j) ar[rr][j] = ap[j];
                    ar24[rr] = (abase + u * ADJP)[24];
                }
            }
            #pragma unroll 2
            for (int t = 0; t < TT_; ++t) {
                const u64* xr = reinterpret_cast<const u64*>(x3row + t * 26);
                u64 xv[12];
                #pragma unroll
                for (int j = 0; j < 12; ++j) xv[j] = xr[j];
                const float x24 = x3row[t * 26 + 24];
                #pragma unroll
                for (int rr = 0; rr < 2; ++rr) {
                    if (rr < np) {
                        u64 a = pack2(0.f, 0.f), b = pack2(0.f, 0.f);
                        #pragma unroll
                        for (int j = 0; j < 6; ++j) {
                            a = fma2(ar[rr][j],     xv[j],     a);
                            b = fma2(ar[rr][j + 6], xv[j + 6], b);
                        }
                        float alo, ahi, blo, bhi;
                        unpack2(a, alo, ahi); unpack2(b, blo, bhi);
                        const float s = fmaf(ar24[rr], x24, (alo + ahi) + (blo + bhi));
                        zbase[t * V_ + (r0 + rr) * 8 + ug] = s;
                    }
                }
            }
        }
    }
}

// ---------------------------------------------------------------------------
extern "C" void kernel_launch(void* const* d_in, const int* in_sizes, int n_in,
                              void* d_out, int out_size) {
    (void)in_sizes; (void)n_in; (void)out_size;
    const float* x  = (const float*)d_in[0];
    const float* A  = (const float*)d_in[1];
    const float* W1 = (const float*)d_in[2];
    const float* b1 = (const float*)d_in[3];
    const float* W2 = (const float*)d_in[4];
    const float* b2 = (const float*)d_in[5];
    const float* W3 = (const float*)d_in[6];
    const float* b3 = (const float*)d_in[7];
    const float* W4 = (const float*)d_in[8];
    const float* b4 = (const float*)d_in[9];
    float* z = (float*)d_out;

    cudaFuncSetAttribute(k3_main, cudaFuncAttributeMaxDynamicSharedMemorySize, 231424);

    k1_tsum<<<N_ * C_, 256>>>(x);
    k2_adj<<<N_, 256>>>(A, W1, b1, W2, b2, W4, b4);
    k3_main<<<N_ * 16, 512, 231424>>>(x, W3, b3, z);
}

// round 3
// speedup vs baseline: 1.3905x; 1.3905x over previous
#include <cuda_runtime.h>

#define N_   128
#define C_   64
#define CO_  64
#define T_   256
#define V_   25
#define R_   8
#define TV_  (T_ * V_)    // 6400
#define ADJP 28
#define TVT  128          // tv tile in k3a

// scratch (device globals -- no allocation allowed)
__device__ float g_xm[N_ * C_ * V_];                    // [n][c][v]
__device__ float g_adj[N_ * CO_ * V_ * ADJP];           // [n][o][u][28]
__device__ float g_x3[(size_t)N_ * CO_ * TV_];          // [n][o][tv]  ~210MB

typedef unsigned long long u64;

__device__ __forceinline__ u64 pack2(float lo, float hi) {
    u64 r; asm("mov.b64 %0, {%1,%2};" : "=l"(r) : "f"(lo), "f"(hi)); return r;
}
__device__ __forceinline__ void unpack2(u64 v, float& lo, float& hi) {
    asm("mov.b64 {%0,%1}, %2;" : "=f"(lo), "=f"(hi) : "l"(v));
}
__device__ __forceinline__ u64 fma2(u64 a, u64 b, u64 c) {
    u64 d; asm("fma.rn.f32x2 %0, %1, %2, %3;" : "=l"(d) : "l"(a), "l"(b), "l"(c)); return d;
}

// ---------------------------------------------------------------------------
// Kernel 1: xm[n,c,v] = sum_t x[n,c,t,v]
// ---------------------------------------------------------------------------
__global__ void k1_tsum(const float* __restrict__ x) {
    __shared__ float tile[TV_];
    __shared__ float part[8][V_];
    const int bx  = blockIdx.x;               // n*64 + c
    const int tid = threadIdx.x;

    const float4* src = reinterpret_cast<const float4*>(x + (size_t)bx * TV_);
    float4* dst = reinterpret_cast<float4*>(tile);
    for (int i = tid; i < TV_ / 4; i += 256) dst[i] = src[i];
    __syncthreads();

    if (tid < 200) {
        const int g = tid / 25, v = tid - g * 25;
        float s = 0.f;
        const int tb = g * 32;
        #pragma unroll 8
        for (int t = tb; t < tb + 32; ++t) s += tile[t * V_ + v];
        part[g][v] = s;
    }
    __syncthreads();

    if (tid < V_) {
        float s = 0.f;
        #pragma unroll
        for (int g = 0; g < 8; ++g) s += part[g][tid];
        g_xm[bx * V_ + tid] = s;
    }
}

// ---------------------------------------------------------------------------
// Kernel 2: adj[n,o,u,v] = sum_r W4[o,r]*tanh(x1[n,r,u]-x2[n,r,v]) + b4[o] + A[u,v]
// ---------------------------------------------------------------------------
__global__ void k2_adj(const float* __restrict__ A,
                       const float* __restrict__ W1, const float* __restrict__ b1,
                       const float* __restrict__ W2, const float* __restrict__ b2,
                       const float* __restrict__ W4, const float* __restrict__ b4) {
    __shared__ float sxm[C_ * V_];
    __shared__ float sx1[R_ * V_];
    __shared__ float sx2[R_ * V_];
    __shared__ float sW4[CO_ * R_];
    __shared__ float sA[V_ * V_];
    __shared__ float sb4[CO_];

    const int n = blockIdx.x, tid = threadIdx.x;
    for (int i = tid; i < C_ * V_;  i += 256) sxm[i] = g_xm[n * C_ * V_ + i];
    for (int i = tid; i < CO_ * R_; i += 256) sW4[i] = W4[i];
    for (int i = tid; i < V_ * V_;  i += 256) sA[i]  = A[i];
    if (tid < CO_) sb4[tid] = b4[tid];
    __syncthreads();

    if (tid < R_ * V_) {
        const int r = tid / V_, v = tid - r * V_;
        float s1 = 0.f, s2 = 0.f;
        for (int c = 0; c < C_; ++c) {
            const float xv = sxm[c * V_ + v];
            s1 = fmaf(W1[r * C_ + c], xv, s1);
            s2 = fmaf(W2[r * C_ + c], xv, s2);
        }
        sx1[tid] = s1 * (1.0f / T_) + b1[r];
        sx2[tid] = s2 * (1.0f / T_) + b2[r];
    }
    __syncthreads();

    for (int p = tid; p < V_ * V_; p += 256) {
        const int u = p / V_, v = p - u * V_;
        float y[R_];
        #pragma unroll
        for (int r = 0; r < R_; ++r) y[r] = tanhf(sx1[r * V_ + u] - sx2[r * V_ + v]);
        const float av = sA[p];
        float* out = &g_adj[((size_t)(n * CO_) * V_ + u) * ADJP + v];
        for (int o = 0; o < CO_; ++o) {
            float s = sb4[o];
            #pragma unroll
            for (int r = 0; r < R_; ++r) s = fmaf(sW4[o * R_ + r], y[r], s);
            out[(size_t)o * V_ * ADJP] = s + av;
        }
    }
}

// ---------------------------------------------------------------------------
// Kernel 3a: x3[n,o,tv] = b3[o] + sum_c W3[o,c] x[n,c,tv]
//   per-n GEMM [64x64]@[64x6400], block tile 64o x 128tv, 128 threads,
//   thread tile 8o x 8tv via f32x2 o-pairs (a-operands are direct u64 LDS).
// dynamic smem: sW 64x66 + sx 64x128 = 49,664 B  ->  4 blocks/SM
// ---------------------------------------------------------------------------
__global__ void __launch_bounds__(128, 4)
k3a_gemm(const float* __restrict__ x, const float* __restrict__ W3,
         const float* __restrict__ b3) {
    extern __shared__ float sm[];
    float* sW = sm;             // [c][o] stride 66
    float* sx = sm + 64 * 66;   // [c][tv] stride 128

    const int blk  = blockIdx.x;
    const int n    = blk / 50;
    const int tv0  = (blk - n * 50) * TVT;
    const int tid  = threadIdx.x;

    for (int i = tid; i < 4096; i += 128) {
        const int o = i >> 6, c = i & 63;
        sW[c * 66 + o] = W3[i];
    }
    const float4* xs = reinterpret_cast<const float4*>(x + (size_t)n * C_ * TV_ + tv0);
    float4* sx4 = reinterpret_cast<float4*>(sx);
    for (int i = tid; i < 64 * 32; i += 128) {
        const int c = i >> 5, j = i & 31;
        sx4[c * 32 + j] = xs[(size_t)c * (TV_ / 4) + j];
    }
    __syncthreads();

    const int tx = tid & 15;      // tv group (8 each)
    const int o0 = (tid >> 4) * 8;

    u64 acc[4][8];
    #pragma unroll
    for (int i = 0; i < 4; ++i)
        #pragma unroll
        for (int j = 0; j < 8; ++j) acc[i][j] = 0ull;

    #pragma unroll 2
    for (int c = 0; c < 64; ++c) {
        const u64* arow = reinterpret_cast<const u64*>(&sW[c * 66 + o0]);
        const u64 a0 = arow[0], a1 = arow[1], a2 = arow[2], a3 = arow[3];
        const float* brow = &sx[c * 128 + tx * 8];
        const float4 bA = *reinterpret_cast<const float4*>(brow);
        const float4 bB = *reinterpret_cast<const float4*>(brow + 4);
        u64 b[8];
        b[0] = pack2(bA.x, bA.x); b[1] = pack2(bA.y, bA.y);
        b[2] = pack2(bA.z, bA.z); b[3] = pack2(bA.w, bA.w);
        b[4] = pack2(bB.x, bB.x); b[5] = pack2(bB.y, bB.y);
        b[6] = pack2(bB.z, bB.z); b[7] = pack2(bB.w, bB.w);
        #pragma unroll
        for (int j = 0; j < 8; ++j) {
            acc[0][j] = fma2(a0, b[j], acc[0][j]);
            acc[1][j] = fma2(a1, b[j], acc[1][j]);
            acc[2][j] = fma2(a2, b[j], acc[2][j]);
            acc[3][j] = fma2(a3, b[j], acc[3][j]);
        }
    }

    // epilogue: unpack o-pairs, add bias, store 8-float rows
    const size_t obase = (size_t)n * CO_ * TV_ + tv0 + tx * 8;
    #pragma unroll
    for (int i = 0; i < 4; ++i) {
        const int oA = o0 + 2 * i, oB = oA + 1;
        const float biasA = b3[oA], biasB = b3[oB];
        float rA[8], rB[8];
        #pragma unroll
        for (int j = 0; j < 8; ++j) {
            unpack2(acc[i][j], rA[j], rB[j]);
            rA[j] += biasA; rB[j] += biasB;
        }
        float4* pA = reinterpret_cast<float4*>(g_x3 + obase + (size_t)oA * TV_);
        float4* pB = reinterpret_cast<float4*>(g_x3 + obase + (size_t)oB * TV_);
        pA[0] = make_float4(rA[0], rA[1], rA[2], rA[3]);
        pA[1] = make_float4(rA[4], rA[5], rA[6], rA[7]);
        pB[0] = make_float4(rB[0], rB[1], rB[2], rB[3]);
        pB[1] = make_float4(rB[4], rB[5], rB[6], rB[7]);
    }
}

// ---------------------------------------------------------------------------
// Kernel 3b: per block (n,o):  z[t,u] = sum_v adj[u,v] * x3[t,v]
//   thread: u = tid%25, t-group tg = tid/25 (10 groups of 26 t's)
//   adj row in 25 registers, x3 tile in smem [256][28]
// static smem: 25*28 + 256*28 = 31,472 B  ->  7 blocks/SM
// ---------------------------------------------------------------------------
__global__ void __launch_bounds__(256)
k3b_apply(float* __restrict__ z) {
    __shared__ float sadj[25 * ADJP];
    __shared__ float sx3[256 * ADJP];

    const int blk = blockIdx.x;       // n*64 + o
    const int tid = threadIdx.x;

    const float* asrc = g_adj + (size_t)blk * (V_ * ADJP);
    for (int i = tid; i < 25 * ADJP; i += 256) sadj[i] = asrc[i];

    const float4* xsrc = reinterpret_cast<const float4*>(g_x3 + (size_t)blk * TV_);
    for (int i = tid; i < TV_ / 4; i += 256) {
        const float4 f = xsrc[i];
        const int e = i * 4;
        float fv[4] = {f.x, f.y, f.z, f.w};
        #pragma unroll
        for (int k = 0; k < 4; ++k) {
            const int ee = e + k;
            const int t = ee / 25, v = ee - t * 25;
            sx3[t * ADJP + v] = fv[k];
        }
    }
    __syncthreads();

    if (tid >= 250) return;
    const int tg = tid / 25;
    const int u  = tid - tg * 25;

    // adj[u,:] into registers
    float a[25];
    {
        const float* ar = &sadj[u * ADJP];
        #pragma unroll
        for (int j = 0; j < 6; ++j) {
            const float4 f = *reinterpret_cast<const float4*>(ar + 4 * j);
            a[4*j] = f.x; a[4*j+1] = f.y; a[4*j+2] = f.z; a[4*j+3] = f.w;
        }
        a[24] = ar[24];
    }

    float* zb = z + (size_t)blk * TV_;
    const int tbeg = tg * 26;
    const int tcnt = (tbeg + 26 <= T_) ? 26 : (T_ - tbeg);
    for (int k = 0; k < tcnt; ++k) {
        const int t = tbeg + k;
        const float* xr = &sx3[t * ADJP];
        float xv[25];
        #pragma unroll
        for (int j = 0; j < 6; ++j) {
            const float4 f = *reinterpret_cast<const float4*>(xr + 4 * j);
            xv[4*j] = f.x; xv[4*j+1] = f.y; xv[4*j+2] = f.z; xv[4*j+3] = f.w;
        }
        xv[24] = xr[24];
        float s = 0.f;
        #pragma unroll
        for (int v = 0; v < 25; ++v) s = fmaf(a[v], xv[v], s);
        zb[t * V_ + u] = s;
    }
}

// ---------------------------------------------------------------------------
extern "C" void kernel_launch(void* const* d_in, const int* in_sizes, int n_in,
                              void* d_out, int out_size) {
    (void)in_sizes; (void)n_in; (void)out_size;
    const float* x  = (const float*)d_in[0];
    const float* A  = (const float*)d_in[1];
    const float* W1 = (const float*)d_in[2];
    const float* b1 = (const float*)d_in[3];
    const float* W2 = (const float*)d_in[4];
    const float* b2 = (const float*)d_in[5];
    const float* W3 = (const float*)d_in[6];
    const float* b3 = (const float*)d_in[7];
    const float* W4 = (const float*)d_in[8];
    const float* b4 = (const float*)d_in[9];
    float* z = (float*)d_out;

    cudaFuncSetAttribute(k3a_gemm, cudaFuncAttributeMaxDynamicSharedMemorySize, 49664);

    k1_tsum<<<N_ * C_, 256>>>(x);
    k2_adj<<<N_, 256>>>(A, W1, b1, W2, b2, W4, b4);
    k3a_gemm<<<N_ * 50, 128, 49664>>>(x, W3, b3);
    k3b_apply<<<N_ * CO_, 256>>>(z);
}

// round 4
// speedup vs baseline: 1.4806x; 1.0648x over previous
#include <cuda_runtime.h>

#define N_   128
#define C_   64
#define CO_  64
#define T_   256
#define V_   25
#define R_   8
#define TV_  (T_ * V_)    // 6400
#define ADJP 28
#define TVT  128          // tv tile in k3a

// scratch (device globals -- no allocation allowed)
__device__ float g_xm[N_ * C_ * V_];                    // [n][c][v]
__device__ float g_adj[N_ * CO_ * V_ * ADJP];           // [n][o][u][28]
__device__ float g_x3[(size_t)N_ * CO_ * TV_];          // [n][o][tv]  ~210MB

typedef unsigned long long u64;

__device__ __forceinline__ u64 pack2(float lo, float hi) {
    u64 r; asm("mov.b64 %0, {%1,%2};" : "=l"(r) : "f"(lo), "f"(hi)); return r;
}
__device__ __forceinline__ void unpack2(u64 v, float& lo, float& hi) {
    asm("mov.b64 {%0,%1}, %2;" : "=f"(lo), "=f"(hi) : "l"(v));
}
__device__ __forceinline__ u64 fma2(u64 a, u64 b, u64 c) {
    u64 d; asm("fma.rn.f32x2 %0, %1, %2, %3;" : "=l"(d) : "l"(a), "l"(b), "l"(c)); return d;
}

// ---------------------------------------------------------------------------
// Kernel 1: xm[n,c,v] = sum_t x[n,c,t,v]
// ---------------------------------------------------------------------------
__global__ void k1_tsum(const float* __restrict__ x) {
    __shared__ float tile[TV_];
    __shared__ float part[8][V_];
    const int bx  = blockIdx.x;               // n*64 + c
    const int tid = threadIdx.x;

    const float4* src = reinterpret_cast<const float4*>(x + (size_t)bx * TV_);
    float4* dst = reinterpret_cast<float4*>(tile);
    for (int i = tid; i < TV_ / 4; i += 256) dst[i] = src[i];
    __syncthreads();

    if (tid < 200) {
        const int g = tid / 25, v = tid - g * 25;
        float s = 0.f;
        const int tb = g * 32;
        #pragma unroll 8
        for (int t = tb; t < tb + 32; ++t) s += tile[t * V_ + v];
        part[g][v] = s;
    }
    __syncthreads();

    if (tid < V_) {
        float s = 0.f;
        #pragma unroll
        for (int g = 0; g < 8; ++g) s += part[g][tid];
        g_xm[bx * V_ + tid] = s;
    }
}

// ---------------------------------------------------------------------------
// Kernel 2: adj[n,o,u,v] = sum_r W4[o,r]*tanh(x1[n,r,u]-x2[n,r,v]) + b4[o] + A[u,v]
// ---------------------------------------------------------------------------
__global__ void k2_adj(const float* __restrict__ A,
                       const float* __restrict__ W1, const float* __restrict__ b1,
                       const float* __restrict__ W2, const float* __restrict__ b2,
                       const float* __restrict__ W4, const float* __restrict__ b4) {
    __shared__ float sxm[C_ * V_];
    __shared__ float sx1[R_ * V_];
    __shared__ float sx2[R_ * V_];
    __shared__ float sW4[CO_ * R_];
    __shared__ float sA[V_ * V_];
    __shared__ float sb4[CO_];

    const int n = blockIdx.x, tid = threadIdx.x;
    for (int i = tid; i < C_ * V_;  i += 256) sxm[i] = g_xm[n * C_ * V_ + i];
    for (int i = tid; i < CO_ * R_; i += 256) sW4[i] = W4[i];
    for (int i = tid; i < V_ * V_;  i += 256) sA[i]  = A[i];
    if (tid < CO_) sb4[tid] = b4[tid];
    __syncthreads();

    if (tid < R_ * V_) {
        const int r = tid / V_, v = tid - r * V_;
        float s1 = 0.f, s2 = 0.f;
        for (int c = 0; c < C_; ++c) {
            const float xv = sxm[c * V_ + v];
            s1 = fmaf(W1[r * C_ + c], xv, s1);
            s2 = fmaf(W2[r * C_ + c], xv, s2);
        }
        sx1[tid] = s1 * (1.0f / T_) + b1[r];
        sx2[tid] = s2 * (1.0f / T_) + b2[r];
    }
    __syncthreads();

    for (int p = tid; p < V_ * V_; p += 256) {
        const int u = p / V_, v = p - u * V_;
        float y[R_];
        #pragma unroll
        for (int r = 0; r < R_; ++r) y[r] = tanhf(sx1[r * V_ + u] - sx2[r * V_ + v]);
        const float av = sA[p];
        float* out = &g_adj[((size_t)(n * CO_) * V_ + u) * ADJP + v];
        for (int o = 0; o < CO_; ++o) {
            float s = sb4[o];
            #pragma unroll
            for (int r = 0; r < R_; ++r) s = fmaf(sW4[o * R_ + r], y[r], s);
            out[(size_t)o * V_ * ADJP] = s + av;
        }
    }
}

// ---------------------------------------------------------------------------
// Kernel 3a: x3[n,o,tv] = b3[o] + sum_c W3[o,c] x[n,c,tv]
//   per-n GEMM [64x64]@[64x6400], block tile 64o x 128tv, 128 threads,
//   thread tile 8o x 8tv via f32x2 o-pairs.
// ---------------------------------------------------------------------------
__global__ void __launch_bounds__(128, 4)
k3a_gemm(const float* __restrict__ x, const float* __restrict__ W3,
         const float* __restrict__ b3) {
    extern __shared__ float sm[];
    float* sW = sm;             // [c][o] stride 66
    float* sx = sm + 64 * 66;   // [c][tv] stride 128

    const int blk  = blockIdx.x;
    const int n    = blk / 50;
    const int tv0  = (blk - n * 50) * TVT;
    const int tid  = threadIdx.x;

    for (int i = tid; i < 4096; i += 128) {
        const int o = i >> 6, c = i & 63;
        sW[c * 66 + o] = W3[i];
    }
    const float4* xs = reinterpret_cast<const float4*>(x + (size_t)n * C_ * TV_ + tv0);
    float4* sx4 = reinterpret_cast<float4*>(sx);
    for (int i = tid; i < 64 * 32; i += 128) {
        const int c = i >> 5, j = i & 31;
        sx4[c * 32 + j] = xs[(size_t)c * (TV_ / 4) + j];
    }
    __syncthreads();

    const int tx = tid & 15;      // tv group (8 each)
    const int o0 = (tid >> 4) * 8;

    u64 acc[4][8];
    #pragma unroll
    for (int i = 0; i < 4; ++i)
        #pragma unroll
        for (int j = 0; j < 8; ++j) acc[i][j] = 0ull;

    #pragma unroll 4
    for (int c = 0; c < 64; ++c) {
        const u64* arow = reinterpret_cast<const u64*>(&sW[c * 66 + o0]);
        const u64 a0 = arow[0], a1 = arow[1], a2 = arow[2], a3 = arow[3];
        const float* brow = &sx[c * 128 + tx * 8];
        const float4 bA = *reinterpret_cast<const float4*>(brow);
        const float4 bB = *reinterpret_cast<const float4*>(brow + 4);
        u64 b[8];
        b[0] = pack2(bA.x, bA.x); b[1] = pack2(bA.y, bA.y);
        b[2] = pack2(bA.z, bA.z); b[3] = pack2(bA.w, bA.w);
        b[4] = pack2(bB.x, bB.x); b[5] = pack2(bB.y, bB.y);
        b[6] = pack2(bB.z, bB.z); b[7] = pack2(bB.w, bB.w);
        #pragma unroll
        for (int j = 0; j < 8; ++j) {
            acc[0][j] = fma2(a0, b[j], acc[0][j]);
            acc[1][j] = fma2(a1, b[j], acc[1][j]);
            acc[2][j] = fma2(a2, b[j], acc[2][j]);
            acc[3][j] = fma2(a3, b[j], acc[3][j]);
        }
    }

    const size_t obase = (size_t)n * CO_ * TV_ + tv0 + tx * 8;
    #pragma unroll
    for (int i = 0; i < 4; ++i) {
        const int oA = o0 + 2 * i, oB = oA + 1;
        const float biasA = b3[oA], biasB = b3[oB];
        float rA[8], rB[8];
        #pragma unroll
        for (int j = 0; j < 8; ++j) {
            unpack2(acc[i][j], rA[j], rB[j]);
            rA[j] += biasA; rB[j] += biasB;
        }
        float4* pA = reinterpret_cast<float4*>(g_x3 + obase + (size_t)oA * TV_);
        float4* pB = reinterpret_cast<float4*>(g_x3 + obase + (size_t)oB * TV_);
        pA[0] = make_float4(rA[0], rA[1], rA[2], rA[3]);
        pA[1] = make_float4(rA[4], rA[5], rA[6], rA[7]);
        pB[0] = make_float4(rB[0], rB[1], rB[2], rB[3]);
        pB[1] = make_float4(rB[4], rB[5], rB[6], rB[7]);
    }
}

// ---------------------------------------------------------------------------
// Kernel 3b: per block (n,o):  z[t,u] = sum_v adj[u,v] * x3[t,v]
//   thread: u = tid%25, t-group tg = tid/25; 2-t unroll, dual accumulators
//   -> 4 independent FMA chains per thread.
// ---------------------------------------------------------------------------
__global__ void __launch_bounds__(256, 4)
k3b_apply(float* __restrict__ z) {
    __shared__ float sadj[25 * ADJP];
    __shared__ float sx3[256 * ADJP];

    const int blk = blockIdx.x;       // n*64 + o
    const int tid = threadIdx.x;

    const float* asrc = g_adj + (size_t)blk * (V_ * ADJP);
    for (int i = tid; i < 25 * ADJP; i += 256) sadj[i] = asrc[i];

    const float4* xsrc = reinterpret_cast<const float4*>(g_x3 + (size_t)blk * TV_);
    for (int i = tid; i < TV_ / 4; i += 256) {
        const float4 f = xsrc[i];
        const int e = i * 4;
        float fv[4] = {f.x, f.y, f.z, f.w};
        #pragma unroll
        for (int k = 0; k < 4; ++k) {
            const int ee = e + k;
            const int t = ee / 25, v = ee - t * 25;
            sx3[t * ADJP + v] = fv[k];
        }
    }
    __syncthreads();

    if (tid >= 250) return;
    const int tg = tid / 25;
    const int u  = tid - tg * 25;

    // adj[u,:] into registers
    float a[25];
    {
        const float* ar = &sadj[u * ADJP];
        #pragma unroll
        for (int j = 0; j < 6; ++j) {
            const float4 f = *reinterpret_cast<const float4*>(ar + 4 * j);
            a[4*j] = f.x; a[4*j+1] = f.y; a[4*j+2] = f.z; a[4*j+3] = f.w;
        }
        a[24] = ar[24];
    }

    float* zb = z + (size_t)blk * TV_;
    const int tbeg  = tg * 26;
    const int npair = ((tbeg + 26 <= T_) ? 26 : (T_ - tbeg)) >> 1;   // 13 or 11

    for (int k = 0; k < npair; ++k) {
        const int t = tbeg + 2 * k;
        const float* x0 = &sx3[t * ADJP];
        const float* x1 = x0 + ADJP;
        float s0a = 0.f, s0b = 0.f, s1a = 0.f, s1b = 0.f;
        #pragma unroll
        for (int j = 0; j < 3; ++j) {
            const float4 f0 = *reinterpret_cast<const float4*>(x0 + 4 * j);
            const float4 f1 = *reinterpret_cast<const float4*>(x1 + 4 * j);
            const float4 g0 = *reinterpret_cast<const float4*>(x0 + 12 + 4 * j);
            const float4 g1 = *reinterpret_cast<const float4*>(x1 + 12 + 4 * j);
            s0a = fmaf(a[4*j+0], f0.x, s0a); s0a = fmaf(a[4*j+1], f0.y, s0a);
            s0a = fmaf(a[4*j+2], f0.z, s0a); s0a = fmaf(a[4*j+3], f0.w, s0a);
            s1a = fmaf(a[4*j+0], f1.x, s1a); s1a = fmaf(a[4*j+1], f1.y, s1a);
            s1a = fmaf(a[4*j+2], f1.z, s1a); s1a = fmaf(a[4*j+3], f1.w, s1a);
            s0b = fmaf(a[12+4*j+0], g0.x, s0b); s0b = fmaf(a[12+4*j+1], g0.y, s0b);
            s0b = fmaf(a[12+4*j+2], g0.z, s0b); s0b = fmaf(a[12+4*j+3], g0.w, s0b);
            s1b = fmaf(a[12+4*j+0], g1.x, s1b); s1b = fmaf(a[12+4*j+1], g1.y, s1b);
            s1b = fmaf(a[12+4*j+2], g1.z, s1b); s1b = fmaf(a[12+4*j+3], g1.w, s1b);
        }
        s0a = fmaf(a[24], x0[24], s0a);
        s1a = fmaf(a[24], x1[24], s1a);
        zb[t * V_ + u]       = s0a + s0b;
        zb[(t + 1) * V_ + u] = s1a + s1b;
    }
}

// ---------------------------------------------------------------------------
extern "C" void kernel_launch(void* const* d_in, const int* in_sizes, int n_in,
                              void* d_out, int out_size) {
    (void)in_sizes; (void)n_in; (void)out_size;
    const float* x  = (const float*)d_in[0];
    const float* A  = (const float*)d_in[1];
    const float* W1 = (const float*)d_in[2];
    const float* b1 = (const float*)d_in[3];
    const float* W2 = (const float*)d_in[4];
    const float* b2 = (const float*)d_in[5];
    const float* W3 = (const float*)d_in[6];
    const float* b3 = (const float*)d_in[7];
    const float* W4 = (const float*)d_in[8];
    const float* b4 = (const float*)d_in[9];
    float* z = (float*)d_out;

    cudaFuncSetAttribute(k3a_gemm, cudaFuncAttributeMaxDynamicSharedMemorySize, 49664);

    k1_tsum<<<N_ * C_, 256>>>(x);
    k2_adj<<<N_, 256>>>(A, W1, b1, W2, b2, W4, b4);
    k3a_gemm<<<N_ * 50, 128, 49664>>>(x, W3, b3);
    k3b_apply<<<N_ * CO_, 256>>>(z);
}

// round 5
// speedup vs baseline: 1.4942x; 1.0092x over previous
#include <cuda_runtime.h>

#define N_   128
#define C_   64
#define CO_  64
#define T_   256
#define V_   25
#define R_   8
#define TV_  (T_ * V_)    // 6400
#define ADJP 28
#define TVT  128          // tv tile in k3a

// scratch (device globals -- no allocation allowed)
__device__ float g_xm[N_ * C_ * V_];                    // [n][c][v]
__device__ float g_adj[N_ * CO_ * V_ * ADJP];           // [n][o][u][28]
__device__ float g_x3[(size_t)N_ * CO_ * TV_];          // [n][o][tv]  ~210MB

typedef unsigned long long u64;

__device__ __forceinline__ u64 pack2(float lo, float hi) {
    u64 r; asm("mov.b64 %0, {%1,%2};" : "=l"(r) : "f"(lo), "f"(hi)); return r;
}
__device__ __forceinline__ void unpack2(u64 v, float& lo, float& hi) {
    asm("mov.b64 {%0,%1}, %2;" : "=f"(lo), "=f"(hi) : "l"(v));
}
__device__ __forceinline__ u64 fma2(u64 a, u64 b, u64 c) {
    u64 d; asm("fma.rn.f32x2 %0, %1, %2, %3;" : "=l"(d) : "l"(a), "l"(b), "l"(c)); return d;
}

// ---------------------------------------------------------------------------
// Kernel 1: xm[n,c,v] = sum_t x[n,c,t,v]
// ---------------------------------------------------------------------------
__global__ void k1_tsum(const float* __restrict__ x) {
    __shared__ float tile[TV_];
    __shared__ float part[8][V_];
    const int bx  = blockIdx.x;               // n*64 + c
    const int tid = threadIdx.x;

    const float4* src = reinterpret_cast<const float4*>(x + (size_t)bx * TV_);
    float4* dst = reinterpret_cast<float4*>(tile);
    for (int i = tid; i < TV_ / 4; i += 256) dst[i] = src[i];
    __syncthreads();

    if (tid < 200) {
        const int g = tid / 25, v = tid - g * 25;
        float s = 0.f;
        const int tb = g * 32;
        #pragma unroll 8
        for (int t = tb; t < tb + 32; ++t) s += tile[t * V_ + v];
        part[g][v] = s;
    }
    __syncthreads();

    if (tid < V_) {
        float s = 0.f;
        #pragma unroll
        for (int g = 0; g < 8; ++g) s += part[g][tid];
        g_xm[bx * V_ + tid] = s;
    }
}

// ---------------------------------------------------------------------------
// Kernel 2: adj[n,o,u,v] = sum_r W4[o,r]*tanh(x1[n,r,u]-x2[n,r,v]) + b4[o] + A[u,v]
// ---------------------------------------------------------------------------
__global__ void k2_adj(const float* __restrict__ A,
                       const float* __restrict__ W1, const float* __restrict__ b1,
                       const float* __restrict__ W2, const float* __restrict__ b2,
                       const float* __restrict__ W4, const float* __restrict__ b4) {
    __shared__ float sxm[C_ * V_];
    __shared__ float sx1[R_ * V_];
    __shared__ float sx2[R_ * V_];
    __shared__ float sW4[CO_ * R_];
    __shared__ float sA[V_ * V_];
    __shared__ float sb4[CO_];

    const int n = blockIdx.x, tid = threadIdx.x;
    for (int i = tid; i < C_ * V_;  i += 256) sxm[i] = g_xm[n * C_ * V_ + i];
    for (int i = tid; i < CO_ * R_; i += 256) sW4[i] = W4[i];
    for (int i = tid; i < V_ * V_;  i += 256) sA[i]  = A[i];
    if (tid < CO_) sb4[tid] = b4[tid];
    __syncthreads();

    if (tid < R_ * V_) {
        const int r = tid / V_, v = tid - r * V_;
        float s1 = 0.f, s2 = 0.f;
        for (int c = 0; c < C_; ++c) {
            const float xv = sxm[c * V_ + v];
            s1 = fmaf(W1[r * C_ + c], xv, s1);
            s2 = fmaf(W2[r * C_ + c], xv, s2);
        }
        sx1[tid] = s1 * (1.0f / T_) + b1[r];
        sx2[tid] = s2 * (1.0f / T_) + b2[r];
    }
    __syncthreads();

    for (int p = tid; p < V_ * V_; p += 256) {
        const int u = p / V_, v = p - u * V_;
        float y[R_];
        #pragma unroll
        for (int r = 0; r < R_; ++r) y[r] = tanhf(sx1[r * V_ + u] - sx2[r * V_ + v]);
        const float av = sA[p];
        float* out = &g_adj[((size_t)(n * CO_) * V_ + u) * ADJP + v];
        for (int o = 0; o < CO_; ++o) {
            float s = sb4[o];
            #pragma unroll
            for (int r = 0; r < R_; ++r) s = fmaf(sW4[o * R_ + r], y[r], s);
            out[(size_t)o * V_ * ADJP] = s + av;
        }
    }
}

// ---------------------------------------------------------------------------
// Kernel 3a: x3[n,o,tv] = b3[o] + sum_c W3[o,c] x[n,c,tv]
//   per-n GEMM [64x64]@[64x6400], block tile 64o x 128tv, 128 threads,
//   thread tile 8o x 8tv via f32x2 o-pairs.
// ---------------------------------------------------------------------------
__global__ void __launch_bounds__(128, 4)
k3a_gemm(const float* __restrict__ x, const float* __restrict__ W3,
         const float* __restrict__ b3) {
    extern __shared__ float sm[];
    float* sW = sm;             // [c][o] stride 66
    float* sx = sm + 64 * 66;   // [c][tv] stride 128

    const int blk  = blockIdx.x;
    const int n    = blk / 50;
    const int tv0  = (blk - n * 50) * TVT;
    const int tid  = threadIdx.x;

    for (int i = tid; i < 4096; i += 128) {
        const int o = i >> 6, c = i & 63;
        sW[c * 66 + o] = W3[i];
    }
    const float4* xs = reinterpret_cast<const float4*>(x + (size_t)n * C_ * TV_ + tv0);
    float4* sx4 = reinterpret_cast<float4*>(sx);
    for (int i = tid; i < 64 * 32; i += 128) {
        const int c = i >> 5, j = i & 31;
        sx4[c * 32 + j] = xs[(size_t)c * (TV_ / 4) + j];
    }
    __syncthreads();

    const int tx = tid & 15;      // tv group (8 each)
    const int o0 = (tid >> 4) * 8;

    u64 acc[4][8];
    #pragma unroll
    for (int i = 0; i < 4; ++i)
        #pragma unroll
        for (int j = 0; j < 8; ++j) acc[i][j] = 0ull;

    #pragma unroll 4
    for (int c = 0; c < 64; ++c) {
        const u64* arow = reinterpret_cast<const u64*>(&sW[c * 66 + o0]);
        const u64 a0 = arow[0], a1 = arow[1], a2 = arow[2], a3 = arow[3];
        const float* brow = &sx[c * 128 + tx * 8];
        const float4 bA = *reinterpret_cast<const float4*>(brow);
        const float4 bB = *reinterpret_cast<const float4*>(brow + 4);
        u64 b[8];
        b[0] = pack2(bA.x, bA.x); b[1] = pack2(bA.y, bA.y);
        b[2] = pack2(bA.z, bA.z); b[3] = pack2(bA.w, bA.w);
        b[4] = pack2(bB.x, bB.x); b[5] = pack2(bB.y, bB.y);
        b[6] = pack2(bB.z, bB.z); b[7] = pack2(bB.w, bB.w);
        #pragma unroll
        for (int j = 0; j < 8; ++j) {
            acc[0][j] = fma2(a0, b[j], acc[0][j]);
            acc[1][j] = fma2(a1, b[j], acc[1][j]);
            acc[2][j] = fma2(a2, b[j], acc[2][j]);
            acc[3][j] = fma2(a3, b[j], acc[3][j]);
        }
    }

    const size_t obase = (size_t)n * CO_ * TV_ + tv0 + tx * 8;
    #pragma unroll
    for (int i = 0; i < 4; ++i) {
        const int oA = o0 + 2 * i, oB = oA + 1;
        const float biasA = b3[oA], biasB = b3[oB];
        float rA[8], rB[8];
        #pragma unroll
        for (int j = 0; j < 8; ++j) {
            unpack2(acc[i][j], rA[j], rB[j]);
            rA[j] += biasA; rB[j] += biasB;
        }
        float4* pA = reinterpret_cast<float4*>(g_x3 + obase + (size_t)oA * TV_);
        float4* pB = reinterpret_cast<float4*>(g_x3 + obase + (size_t)oB * TV_);
        pA[0] = make_float4(rA[0], rA[1], rA[2], rA[3]);
        pA[1] = make_float4(rA[4], rA[5], rA[6], rA[7]);
        pB[0] = make_float4(rB[0], rB[1], rB[2], rB[3]);
        pB[1] = make_float4(rB[4], rB[5], rB[6], rB[7]);
    }
}

// ---------------------------------------------------------------------------
// Kernel 3b: per block (n,o):  z[t,u] = sum_v adj[u,v] * x3[t,v]
//   thread t (0..255) holds x3[t,:] (25 regs) and all 25 outputs in regs.
//   adj LDS are warp-uniform -> broadcast. No scatter STS, no strided STG.
// ---------------------------------------------------------------------------
__global__ void __launch_bounds__(256, 3)
k3b_apply(float* __restrict__ z) {
    __shared__ float sadj[V_ * ADJP];   // 700
    __shared__ float sbuf[TV_];         // 6400, reused x3 tile -> z tile

    const int blk = blockIdx.x;       // n*64 + o
    const int tid = threadIdx.x;      // = t

    const float* asrc = g_adj + (size_t)blk * (V_ * ADJP);
    for (int i = tid; i < V_ * ADJP; i += 256) sadj[i] = asrc[i];

    const float4* xsrc = reinterpret_cast<const float4*>(g_x3 + (size_t)blk * TV_);
    float4* sbuf4 = reinterpret_cast<float4*>(sbuf);
    for (int i = tid; i < TV_ / 4; i += 256) sbuf4[i] = xsrc[i];
    __syncthreads();

    // x3 row for this t: stride-25 words across lanes -> conflict-free LDS
    float xr[25];
    {
        const float* r = &sbuf[tid * V_];
        #pragma unroll
        for (int v = 0; v < 25; ++v) xr[v] = r[v];
    }

    float acc[25];
    #pragma unroll
    for (int u = 0; u < 25; ++u) {
        const float4* ar = reinterpret_cast<const float4*>(&sadj[u * ADJP]);
        float s = 0.f;
        #pragma unroll
        for (int j = 0; j < 6; ++j) {
            const float4 a = ar[j];
            s = fmaf(a.x, xr[4*j+0], s);
            s = fmaf(a.y, xr[4*j+1], s);
            s = fmaf(a.z, xr[4*j+2], s);
            s = fmaf(a.w, xr[4*j+3], s);
        }
        acc[u] = fmaf(sadj[u * ADJP + 24], xr[24], s);
    }
    __syncthreads();

    // stage z rows in smem (conflict-free stride-25 STS), then coalesced STG
    {
        float* r = &sbuf[tid * V_];
        #pragma unroll
        for (int u = 0; u < 25; ++u) r[u] = acc[u];
    }
    __syncthreads();

    float4* zb = reinterpret_cast<float4*>(z + (size_t)blk * TV_);
    for (int i = tid; i < TV_ / 4; i += 256) zb[i] = sbuf4[i];
}

// ---------------------------------------------------------------------------
extern "C" void kernel_launch(void* const* d_in, const int* in_sizes, int n_in,
                              void* d_out, int out_size) {
    (void)in_sizes; (void)n_in; (void)out_size;
    const float* x  = (const float*)d_in[0];
    const float* A  = (const float*)d_in[1];
    const float* W1 = (const float*)d_in[2];
    const float* b1 = (const float*)d_in[3];
    const float* W2 = (const float*)d_in[4];
    const float* b2 = (const float*)d_in[5];
    const float* W3 = (const float*)d_in[6];
    const float* b3 = (const float*)d_in[7];
    const float* W4 = (const float*)d_in[8];
    const float* b4 = (const float*)d_in[9];
    float* z = (float*)d_out;

    cudaFuncSetAttribute(k3a_gemm, cudaFuncAttributeMaxDynamicSharedMemorySize, 49664);

    k1_tsum<<<N_ * C_, 256>>>(x);
    k2_adj<<<N_, 256>>>(A, W1, b1, W2, b2, W4, b4);
    k3a_gemm<<<N_ * 50, 128, 49664>>>(x, W3, b3);
    k3b_apply<<<N_ * CO_, 256>>>(z);
}

// round 6
// speedup vs baseline: 1.6098x; 1.0773x over previous
#include <cuda_runtime.h>

#define N_   128
#define C_   64
#define CO_  64
#define T_   256
#define V_   25
#define R_   8
#define TV_  (T_ * V_)    // 6400
#define ADJP 28
#define TVT  128          // tv tile in k3a

// scratch (device globals -- no allocation allowed)
__device__ float g_xm[N_ * C_ * V_];                    // [n][c][v]
__device__ float g_adj[N_ * CO_ * V_ * ADJP];           // [n][o][u][28]
__device__ float g_x3[(size_t)N_ * CO_ * TV_];          // [n][o][tv]  ~210MB

typedef unsigned long long u64;

__device__ __forceinline__ u64 pack2(float lo, float hi) {
    u64 r; asm("mov.b64 %0, {%1,%2};" : "=l"(r) : "f"(lo), "f"(hi)); return r;
}
__device__ __forceinline__ void unpack2(u64 v, float& lo, float& hi) {
    asm("mov.b64 {%0,%1}, %2;" : "=f"(lo), "=f"(hi) : "l"(v));
}
__device__ __forceinline__ u64 fma2(u64 a, u64 b, u64 c) {
    u64 d; asm("fma.rn.f32x2 %0, %1, %2, %3;" : "=l"(d) : "l"(a), "l"(b), "l"(c)); return d;
}

// ---------------------------------------------------------------------------
// Kernel 1: xm[n,c,v] = sum_t x[n,c,t,v]
// ---------------------------------------------------------------------------
__global__ void k1_tsum(const float* __restrict__ x) {
    __shared__ float tile[TV_];
    __shared__ float part[8][V_];
    const int bx  = blockIdx.x;               // n*64 + c
    const int tid = threadIdx.x;

    const float4* src = reinterpret_cast<const float4*>(x + (size_t)bx * TV_);
    float4* dst = reinterpret_cast<float4*>(tile);
    for (int i = tid; i < TV_ / 4; i += 256) dst[i] = src[i];
    __syncthreads();

    if (tid < 200) {
        const int g = tid / 25, v = tid - g * 25;
        float s = 0.f;
        const int tb = g * 32;
        #pragma unroll 8
        for (int t = tb; t < tb + 32; ++t) s += tile[t * V_ + v];
        part[g][v] = s;
    }
    __syncthreads();

    if (tid < V_) {
        float s = 0.f;
        #pragma unroll
        for (int g = 0; g < 8; ++g) s += part[g][tid];
        g_xm[bx * V_ + tid] = s;
    }
}

// ---------------------------------------------------------------------------
// Kernel 2: adj[n,o,u,v] = sum_r W4[o,r]*tanh(x1[n,r,u]-x2[n,r,v]) + b4[o] + A[u,v]
//   also zeroes pad lanes v=25..27 (consumed as FFMA2 pad pair in k3b).
// ---------------------------------------------------------------------------
__global__ void k2_adj(const float* __restrict__ A,
                       const float* __restrict__ W1, const float* __restrict__ b1,
                       const float* __restrict__ W2, const float* __restrict__ b2,
                       const float* __restrict__ W4, const float* __restrict__ b4) {
    __shared__ float sxm[C_ * V_];
    __shared__ float sx1[R_ * V_];
    __shared__ float sx2[R_ * V_];
    __shared__ float sW4[CO_ * R_];
    __shared__ float sA[V_ * V_];
    __shared__ float sb4[CO_];

    const int n = blockIdx.x, tid = threadIdx.x;
    for (int i = tid; i < C_ * V_;  i += 256) sxm[i] = g_xm[n * C_ * V_ + i];
    for (int i = tid; i < CO_ * R_; i += 256) sW4[i] = W4[i];
    for (int i = tid; i < V_ * V_;  i += 256) sA[i]  = A[i];
    if (tid < CO_) sb4[tid] = b4[tid];
    __syncthreads();

    if (tid < R_ * V_) {
        const int r = tid / V_, v = tid - r * V_;
        float s1 = 0.f, s2 = 0.f;
        for (int c = 0; c < C_; ++c) {
            const float xv = sxm[c * V_ + v];
            s1 = fmaf(W1[r * C_ + c], xv, s1);
            s2 = fmaf(W2[r * C_ + c], xv, s2);
        }
        sx1[tid] = s1 * (1.0f / T_) + b1[r];
        sx2[tid] = s2 * (1.0f / T_) + b2[r];
    }
    __syncthreads();

    for (int p = tid; p < V_ * V_; p += 256) {
        const int u = p / V_, v = p - u * V_;
        float y[R_];
        #pragma unroll
        for (int r = 0; r < R_; ++r) y[r] = tanhf(sx1[r * V_ + u] - sx2[r * V_ + v]);
        const float av = sA[p];
        float* out = &g_adj[((size_t)(n * CO_) * V_ + u) * ADJP + v];
        for (int o = 0; o < CO_; ++o) {
            float s = sb4[o];
            #pragma unroll
            for (int r = 0; r < R_; ++r) s = fmaf(sW4[o * R_ + r], y[r], s);
            out[(size_t)o * V_ * ADJP] = s + av;
        }
    }

    // zero pad lanes v=25..27 of every adj row
    if (tid < 75) {
        const int u = tid / 3, pv = 25 + (tid - (tid / 3) * 3);
        for (int o = 0; o < CO_; ++o)
            g_adj[((size_t)(n * CO_ + o) * V_ + u) * ADJP + pv] = 0.f;
    }
}

// ---------------------------------------------------------------------------
// Kernel 3a: x3[n,o,tv] = b3[o] + sum_c W3[o,c] x[n,c,tv]
// ---------------------------------------------------------------------------
__global__ void __launch_bounds__(128, 4)
k3a_gemm(const float* __restrict__ x, const float* __restrict__ W3,
         const float* __restrict__ b3) {
    extern __shared__ float sm[];
    float* sW = sm;             // [c][o] stride 66
    float* sx = sm + 64 * 66;   // [c][tv] stride 128

    const int blk  = blockIdx.x;
    const int n    = blk / 50;
    const int tv0  = (blk - n * 50) * TVT;
    const int tid  = threadIdx.x;

    for (int i = tid; i < 4096; i += 128) {
        const int o = i >> 6, c = i & 63;
        sW[c * 66 + o] = W3[i];
    }
    const float4* xs = reinterpret_cast<const float4*>(x + (size_t)n * C_ * TV_ + tv0);
    float4* sx4 = reinterpret_cast<float4*>(sx);
    for (int i = tid; i < 64 * 32; i += 128) {
        const int c = i >> 5, j = i & 31;
        sx4[c * 32 + j] = xs[(size_t)c * (TV_ / 4) + j];
    }
    __syncthreads();

    const int tx = tid & 15;      // tv group (8 each)
    const int o0 = (tid >> 4) * 8;

    u64 acc[4][8];
    #pragma unroll
    for (int i = 0; i < 4; ++i)
        #pragma unroll
        for (int j = 0; j < 8; ++j) acc[i][j] = 0ull;

    #pragma unroll 4
    for (int c = 0; c < 64; ++c) {
        const u64* arow = reinterpret_cast<const u64*>(&sW[c * 66 + o0]);
        const u64 a0 = arow[0], a1 = arow[1], a2 = arow[2], a3 = arow[3];
        const float* brow = &sx[c * 128 + tx * 8];
        const float4 bA = *reinterpret_cast<const float4*>(brow);
        const float4 bB = *reinterpret_cast<const float4*>(brow + 4);
        u64 b[8];
        b[0] = pack2(bA.x, bA.x); b[1] = pack2(bA.y, bA.y);
        b[2] = pack2(bA.z, bA.z); b[3] = pack2(bA.w, bA.w);
        b[4] = pack2(bB.x, bB.x); b[5] = pack2(bB.y, bB.y);
        b[6] = pack2(bB.z, bB.z); b[7] = pack2(bB.w, bB.w);
        #pragma unroll
        for (int j = 0; j < 8; ++j) {
            acc[0][j] = fma2(a0, b[j], acc[0][j]);
            acc[1][j] = fma2(a1, b[j], acc[1][j]);
            acc[2][j] = fma2(a2, b[j], acc[2][j]);
            acc[3][j] = fma2(a3, b[j], acc[3][j]);
        }
    }

    const size_t obase = (size_t)n * CO_ * TV_ + tv0 + tx * 8;
    #pragma unroll
    for (int i = 0; i < 4; ++i) {
        const int oA = o0 + 2 * i, oB = oA + 1;
        const float biasA = b3[oA], biasB = b3[oB];
        float rA[8], rB[8];
        #pragma unroll
        for (int j = 0; j < 8; ++j) {
            unpack2(acc[i][j], rA[j], rB[j]);
            rA[j] += biasA; rB[j] += biasB;
        }
        float4* pA = reinterpret_cast<float4*>(g_x3 + obase + (size_t)oA * TV_);
        float4* pB = reinterpret_cast<float4*>(g_x3 + obase + (size_t)oB * TV_);
        pA[0] = make_float4(rA[0], rA[1], rA[2], rA[3]);
        pA[1] = make_float4(rA[4], rA[5], rA[6], rA[7]);
        pB[0] = make_float4(rB[0], rB[1], rB[2], rB[3]);
        pB[1] = make_float4(rB[4], rB[5], rB[6], rB[7]);
    }
}

// ---------------------------------------------------------------------------
// Kernel 3b v3: per block (n,o):  z[t,u] = sum_v adj[u,v] * x3[t,v]
//   thread t: x3 row as 13 u64 v-pairs in regs; adj rows as u64 v-pairs from
//   smem (both 16B-aligned via ADJP=28, pads zero) -> 325 FFMA2, zero movs.
//   One result reg per u -> straight to smem; buffer reused for z staging.
// ---------------------------------------------------------------------------
__global__ void __launch_bounds__(256, 5)
k3b_apply(float* __restrict__ z) {
    __shared__ float sadj[V_ * ADJP];        // [u][28], pads zero
    __shared__ float sbuf[T_ * ADJP];        // [t][28] x3 tile -> flat z tile

    const int blk = blockIdx.x;       // n*64 + o
    const int tid = threadIdx.x;      // = t

    const float* asrc = g_adj + (size_t)blk * (V_ * ADJP);
    for (int i = tid; i < V_ * ADJP; i += 256) sadj[i] = asrc[i];

    // scatter-fill x3 tile into padded rows
    const float4* xsrc = reinterpret_cast<const float4*>(g_x3 + (size_t)blk * TV_);
    for (int i = tid; i < TV_ / 4; i += 256) {
        const float4 f = xsrc[i];
        const int e = i * 4;
        float fv[4] = {f.x, f.y, f.z, f.w};
        #pragma unroll
        for (int k = 0; k < 4; ++k) {
            const int ee = e + k;
            const int t = ee / 25, v = ee - t * 25;
            sbuf[t * ADJP + v] = fv[k];
        }
    }
    sbuf[tid * ADJP + 25] = 0.f;   // zero the pad lane consumed by FFMA2
    __syncthreads();

    // own x3 row -> 13 u64 pairs in registers (row base 112B-aligned)
    u64 xr2[13];
    {
        const u64* r2 = reinterpret_cast<const u64*>(&sbuf[tid * ADJP]);
        #pragma unroll
        for (int j = 0; j < 13; ++j) xr2[j] = r2[j];
    }
    __syncthreads();   // everyone captured their row; sbuf now reusable

    // compute 25 outputs, write straight into flat z staging [t*25 + u]
    float* zrow = &sbuf[tid * V_];
    #pragma unroll
    for (int u = 0; u < 25; ++u) {
        const u64* ar = reinterpret_cast<const u64*>(&sadj[u * ADJP]);
        u64 acc = 0ull;
        #pragma unroll
        for (int j = 0; j < 13; ++j) acc = fma2(ar[j], xr2[j], acc);
        float lo, hi; unpack2(acc, lo, hi);
        zrow[u] = lo + hi;
    }
    __syncthreads();

    // coalesced copy-out
    float4* zb = reinterpret_cast<float4*>(z + (size_t)blk * TV_);
    const float4* s4 = reinterpret_cast<const float4*>(sbuf);
    for (int i = tid; i < TV_ / 4; i += 256) zb[i] = s4[i];
}

// ---------------------------------------------------------------------------
extern "C" void kernel_launch(void* const* d_in, const int* in_sizes, int n_in,
                              void* d_out, int out_size) {
    (void)in_sizes; (void)n_in; (void)out_size;
    const float* x  = (const float*)d_in[0];
    const float* A  = (const float*)d_in[1];
    const float* W1 = (const float*)d_in[2];
    const float* b1 = (const float*)d_in[3];
    const float* W2 = (const float*)d_in[4];
    const float* b2 = (const float*)d_in[5];
    const float* W3 = (const float*)d_in[6];
    const float* b3 = (const float*)d_in[7];
    const float* W4 = (const float*)d_in[8];
    const float* b4 = (const float*)d_in[9];
    float* z = (float*)d_out;

    cudaFuncSetAttribute(k3a_gemm, cudaFuncAttributeMaxDynamicSharedMemorySize, 49664);

    k1_tsum<<<N_ * C_, 256>>>(x);
    k2_adj<<<N_, 256>>>(A, W1, b1, W2, b2, W4, b4);
    k3a_gemm<<<N_ * 50, 128, 49664>>>(x, W3, b3);
    k3b_apply<<<N_ * CO_, 256>>>(z);
}

// round 8
// speedup vs baseline: 1.8340x; 1.1393x over previous
#include <cuda_runtime.h>
#include <cstdint>

#define N_   128
#define C_   64
#define CO_  64
#define T_   256
#define V_   25
#define R_   8
#define TV_  (T_ * V_)    // 6400
#define ADJP 28

// scratch (device globals -- no allocation allowed)
__device__ float g_xm[N_ * C_ * V_];                    // [n][c][v]
__device__ float g_adj[N_ * CO_ * V_ * ADJP];           // [n][o][u][28]
__device__ float g_x3[(size_t)N_ * CO_ * TV_];          // [n][o][tv]  ~210MB

typedef unsigned long long u64;

__device__ __forceinline__ u64 pack2(float lo, float hi) {
    u64 r; asm("mov.b64 %0, {%1,%2};" : "=l"(r) : "f"(lo), "f"(hi)); return r;
}
__device__ __forceinline__ void unpack2(u64 v, float& lo, float& hi) {
    asm("mov.b64 {%0,%1}, %2;" : "=f"(lo), "=f"(hi) : "l"(v));
}
__device__ __forceinline__ u64 fma2(u64 a, u64 b, u64 c) {
    u64 d; asm("fma.rn.f32x2 %0, %1, %2, %3;" : "=l"(d) : "l"(a), "l"(b), "l"(c)); return d;
}
__device__ __forceinline__ uint32_t f2tf32(float f) {
    uint32_t u; asm("cvt.rna.tf32.f32 %0, %1;" : "=r"(u) : "f"(f)); return u;
}
__device__ __forceinline__ void mma_tf32(float c[4], const uint32_t a[4],
                                         uint32_t b0, uint32_t b1) {
    asm volatile(
        "mma.sync.aligned.m16n8k8.row.col.f32.tf32.tf32.f32 "
        "{%0,%1,%2,%3}, {%4,%5,%6,%7}, {%8,%9}, {%0,%1,%2,%3};"
        : "+f"(c[0]), "+f"(c[1]), "+f"(c[2]), "+f"(c[3])
        : "r"(a[0]), "r"(a[1]), "r"(a[2]), "r"(a[3]), "r"(b0), "r"(b1));
}

// k3a smem layout (floats / uint32 words)
#define SA_PITCH 136           // [c][tv] : 8c+tv bank map -> conflict-free frags
#define SB_PITCH 72            // [c][o]  : 8c+o  bank map -> conflict-free frags
#define SA_WORDS (64 * SA_PITCH)            // 8704 (>= stage 128*65 = 8320)
#define SB_WORDS (64 * SB_PITCH)            // 4608
#define K3A_WORDS (SA_WORDS + 2 * SB_WORDS + 64)
#define K3A_SMEM  (K3A_WORDS * 4)           // 71,936 B

// ---------------------------------------------------------------------------
// Kernel 1: xm[n,c,v] = sum_t x[n,c,t,v]
// ---------------------------------------------------------------------------
__global__ void k1_tsum(const float* __restrict__ x) {
    __shared__ float tile[TV_];
    __shared__ float part[8][V_];
    const int bx  = blockIdx.x;               // n*64 + c
    const int tid = threadIdx.x;

    const float4* src = reinterpret_cast<const float4*>(x + (size_t)bx * TV_);
    float4* dst = reinterpret_cast<float4*>(tile);
    for (int i = tid; i < TV_ / 4; i += 256) dst[i] = src[i];
    __syncthreads();

    if (tid < 200) {
        const int g = tid / 25, v = tid - g * 25;
        float s = 0.f;
        const int tb = g * 32;
        #pragma unroll 8
        for (int t = tb; t < tb + 32; ++t) s += tile[t * V_ + v];
        part[g][v] = s;
    }
    __syncthreads();

    if (tid < V_) {
        float s = 0.f;
        #pragma unroll
        for (int g = 0; g < 8; ++g) s += part[g][tid];
        g_xm[bx * V_ + tid] = s;
    }
}

// ---------------------------------------------------------------------------
// Kernel 2: adj[n,o,u,v] = sum_r W4[o,r]*tanh(x1[n,r,u]-x2[n,r,v]) + b4[o] + A[u,v]
// ---------------------------------------------------------------------------
__global__ void k2_adj(const float* __restrict__ A,
                       const float* __restrict__ W1, const float* __restrict__ b1,
                       const float* __restrict__ W2, const float* __restrict__ b2,
                       const float* __restrict__ W4, const float* __restrict__ b4) {
    __shared__ float sxm[C_ * V_];
    __shared__ float sx1[R_ * V_];
    __shared__ float sx2[R_ * V_];
    __shared__ float sW4[CO_ * R_];
    __shared__ float sA[V_ * V_];
    __shared__ float sb4[CO_];

    const int n = blockIdx.x, tid = threadIdx.x;
    for (int i = tid; i < C_ * V_;  i += 256) sxm[i] = g_xm[n * C_ * V_ + i];
    for (int i = tid; i < CO_ * R_; i += 256) sW4[i] = W4[i];
    for (int i = tid; i < V_ * V_;  i += 256) sA[i]  = A[i];
    if (tid < CO_) sb4[tid] = b4[tid];
    __syncthreads();

    if (tid < R_ * V_) {
        const int r = tid / V_, v = tid - r * V_;
        float s1 = 0.f, s2 = 0.f;
        for (int c = 0; c < C_; ++c) {
            const float xv = sxm[c * V_ + v];
            s1 = fmaf(W1[r * C_ + c], xv, s1);
            s2 = fmaf(W2[r * C_ + c], xv, s2);
        }
        sx1[tid] = s1 * (1.0f / T_) + b1[r];
        sx2[tid] = s2 * (1.0f / T_) + b2[r];
    }
    __syncthreads();

    for (int p = tid; p < V_ * V_; p += 256) {
        const int u = p / V_, v = p - u * V_;
        float y[R_];
        #pragma unroll
        for (int r = 0; r < R_; ++r) y[r] = tanhf(sx1[r * V_ + u] - sx2[r * V_ + v]);
        const float av = sA[p];
        float* out = &g_adj[((size_t)(n * CO_) * V_ + u) * ADJP + v];
        for (int o = 0; o < CO_; ++o) {
            float s = sb4[o];
            #pragma unroll
            for (int r = 0; r < R_; ++r) s = fmaf(sW4[o * R_ + r], y[r], s);
            out[(size_t)o * V_ * ADJP] = s + av;
        }
    }

    if (tid < 75) {
        const int u = tid / 3, pv = 25 + (tid - (tid / 3) * 3);
        for (int o = 0; o < CO_; ++o)
            g_adj[((size_t)(n * CO_ + o) * V_ + u) * ADJP + pv] = 0.f;
    }
}

// ---------------------------------------------------------------------------
// Kernel 3a (HMMA tf32): x3[n,o,tv] = b3[o] + sum_c W3[o,c] x[n,c,tv]
//   D[128tv,64o] = A(x^T, tf32) @ B(W3 hi/lo, tf32) via mma.sync m16n8k8.
//   Block = (n, chunk): 5 tiles of 128 tv. 8 warps = 4 tv-groups x 2 o-halves;
//   warp tile = 32tv x 32o (2 m-tiles x 4 n-tiles), W3 split -> 2 passes.
// ---------------------------------------------------------------------------
__global__ void __launch_bounds__(256, 3)
k3a_hmma(const float* __restrict__ x, const float* __restrict__ W3,
         const float* __restrict__ b3) {
    extern __shared__ uint32_t smw[];
    uint32_t* sA   = smw;                         // [c][tv] pitch 136 (reused as stage)
    uint32_t* sBh  = smw + SA_WORDS;              // [c][o] pitch 72
    uint32_t* sBl  = sBh + SB_WORDS;
    float*    sb3  = reinterpret_cast<float*>(sBl + SB_WORDS);   // 64
    float*    stageF = reinterpret_cast<float*>(sA);             // [tv][65]

    const int tid  = threadIdx.x;
    const int wid  = tid >> 5;
    const int lane = tid & 31;
    const int lc   = lane & 3;      // col-in-group
    const int lg   = lane >> 2;     // group (row)
    const int wm   = wid & 3;       // tv group (32 rows)
    const int wn   = wid >> 2;      // o half (32 cols)

    const int blk   = blockIdx.x;   // n*10 + chunk
    const int n     = blk / 10;
    const int chunk = blk - n * 10;

    // B (W3) hi/lo + bias, once per block
    for (int i = tid; i < 4096; i += 256) {
        const int o = i >> 6, c = i & 63;
        const float w = W3[i];
        const uint32_t hb = f2tf32(w);
        const uint32_t lb = f2tf32(w - __uint_as_float(hb));
        sBh[c * SB_PITCH + o] = hb;
        sBl[c * SB_PITCH + o] = lb;
    }
    if (tid < 64) sb3[tid] = b3[tid];

    const float* xg = x + (size_t)n * C_ * TV_;

    for (int tile = 0; tile < 5; ++tile) {
        const int tv0 = (chunk * 5 + tile) * 128;
        __syncthreads();   // stage/copy-out of prev tile done before sA refill

        // sA fill: x^T tile as tf32, [c][tv] pitch 136 (coalesced LDG+STS)
        #pragma unroll 8
        for (int i = 0; i < 32; ++i) {
            const int e = tid + 256 * i;
            const int c = e >> 7, tvl = e & 127;
            sA[c * SA_PITCH + tvl] = f2tf32(xg[(size_t)c * TV_ + tv0 + tvl]);
        }
        __syncthreads();

        float acc[2][4][4];
        #pragma unroll
        for (int mt = 0; mt < 2; ++mt)
            #pragma unroll
            for (int nt = 0; nt < 4; ++nt)
                #pragma unroll
                for (int j = 0; j < 4; ++j) acc[mt][nt][j] = 0.f;

        #pragma unroll
        for (int k0 = 0; k0 < 64; k0 += 8) {
            uint32_t a[2][4];
            #pragma unroll
            for (int mt = 0; mt < 2; ++mt) {
                const int base = (k0 + lc) * SA_PITCH + wm * 32 + mt * 16 + lg;
                a[mt][0] = sA[base];
                a[mt][1] = sA[base + 8];
                a[mt][2] = sA[base + 4 * SA_PITCH];
                a[mt][3] = sA[base + 8 + 4 * SA_PITCH];
            }
            #pragma unroll
            for (int nt = 0; nt < 4; ++nt) {
                const int bbase = (k0 + lc) * SB_PITCH + wn * 32 + nt * 8 + lg;
                const uint32_t bh0 = sBh[bbase], bh1 = sBh[bbase + 4 * SB_PITCH];
                const uint32_t bl0 = sBl[bbase], bl1 = sBl[bbase + 4 * SB_PITCH];
                mma_tf32(acc[0][nt], a[0], bh0, bh1);
                mma_tf32(acc[0][nt], a[0], bl0, bl1);
                mma_tf32(acc[1][nt], a[1], bh0, bh1);
                mma_tf32(acc[1][nt], a[1], bl0, bl1);
            }
        }
        __syncthreads();   // all frag reads of sA done; reuse as stage

        // epilogue: regs + bias -> stage[tv][o] pitch 65
        #pragma unroll
        for (int mt = 0; mt < 2; ++mt) {
            const int row = wm * 32 + mt * 16 + lg;
            #pragma unroll
            for (int nt = 0; nt < 4; ++nt) {
                const int col = wn * 32 + nt * 8 + 2 * lc;
                const float b0v = sb3[col], b1v = sb3[col + 1];
                stageF[row * 65 + col]           = acc[mt][nt][0] + b0v;
                stageF[row * 65 + col + 1]       = acc[mt][nt][1] + b1v;
                stageF[(row + 8) * 65 + col]     = acc[mt][nt][2] + b0v;
                stageF[(row + 8) * 65 + col + 1] = acc[mt][nt][3] + b1v;
            }
        }
        __syncthreads();

        // copy-out: warp w -> o = w*8..w*8+7, coalesced float4 STG
        #pragma unroll
        for (int r = 0; r < 8; ++r) {
            const int o = wid * 8 + r;
            float4 v;
            v.x = stageF[(4 * lane + 0) * 65 + o];
            v.y = stageF[(4 * lane + 1) * 65 + o];
            v.z = stageF[(4 * lane + 2) * 65 + o];
            v.w = stageF[(4 * lane + 3) * 65 + o];
            *reinterpret_cast<float4*>(g_x3 + (size_t)(n * CO_ + o) * TV_ + tv0 + 4 * lane) = v;
        }
    }
}

// ---------------------------------------------------------------------------
// Kernel 3b: per block (n,o):  z[t,u] = sum_v adj[u,v] * x3[t,v]  (f32x2)
// ---------------------------------------------------------------------------
__global__ void __launch_bounds__(256, 5)
k3b_apply(float* __restrict__ z) {
    __shared__ float sadj[V_ * ADJP];        // [u][28], pads zero
    __shared__ float sbuf[T_ * ADJP];        // [t][28] x3 tile -> flat z tile

    const int blk = blockIdx.x;       // n*64 + o
    const int tid = threadIdx.x;      // = t

    const float* asrc = g_adj + (size_t)blk * (V_ * ADJP);
    for (int i = tid; i < V_ * ADJP; i += 256) sadj[i] = asrc[i];

    const float4* xsrc = reinterpret_cast<const float4*>(g_x3 + (size_t)blk * TV_);
    for (int i = tid; i < TV_ / 4; i += 256) {
        const float4 f = xsrc[i];
        const int e = i * 4;
        float fv[4] = {f.x, f.y, f.z, f.w};
        #pragma unroll
        for (int k = 0; k < 4; ++k) {
            const int ee = e + k;
            const int t = ee / 25, v = ee - t * 25;
            sbuf[t * ADJP + v] = fv[k];
        }
    }
    sbuf[tid * ADJP + 25] = 0.f;
    __syncthreads();

    u64 xr2[13];
    {
        const u64* r2 = reinterpret_cast<const u64*>(&sbuf[tid * ADJP]);
        #pragma unroll
        for (int j = 0; j < 13; ++j) xr2[j] = r2[j];
    }
    __syncthreads();

    float* zrow = &sbuf[tid * V_];
    #pragma unroll
    for (int u = 0; u < 25; ++u) {
        const u64* ar = reinterpret_cast<const u64*>(&sadj[u * ADJP]);
        u64 acc = 0ull;
        #pragma unroll
        for (int j = 0; j < 13; ++j) acc = fma2(ar[j], xr2[j], acc);
        float lo, hi; unpack2(acc, lo, hi);
        zrow[u] = lo + hi;
    }
    __syncthreads();

    float4* zb = reinterpret_cast<float4*>(z + (size_t)blk * TV_);
    const float4* s4 = reinterpret_cast<const float4*>(sbuf);
    for (int i = tid; i < TV_ / 4; i += 256) zb[i] = s4[i];
}

// ---------------------------------------------------------------------------
extern "C" void kernel_launch(void* const* d_in, const int* in_sizes, int n_in,
                              void* d_out, int out_size) {
    (void)in_sizes; (void)n_in; (void)out_size;
    const float* x  = (const float*)d_in[0];
    const float* A  = (const float*)d_in[1];
    const float* W1 = (const float*)d_in[2];
    const float* b1 = (const float*)d_in[3];
    const float* W2 = (const float*)d_in[4];
    const float* b2 = (const float*)d_in[5];
    const float* W3 = (const float*)d_in[6];
    const float* b3 = (const float*)d_in[7];
    const float* W4 = (const float*)d_in[8];
    const float* b4 = (const float*)d_in[9];
    float* z = (float*)d_out;

    cudaFuncSetAttribute(k3a_hmma, cudaFuncAttributeMaxDynamicSharedMemorySize, K3A_SMEM);

    k1_tsum<<<N_ * C_, 256>>>(x);
    k2_adj<<<N_, 256>>>(A, W1, b1, W2, b2, W4, b4);
    k3a_hmma<<<N_ * 10, 256, K3A_SMEM>>>(x, W3, b3);
    k3b_apply<<<N_ * CO_, 256>>>(z);
}